// round 8
// baseline (speedup 1.0000x reference)
#include <cuda_runtime.h>

#define INF 6
#define OUTF 64
static constexpr float BN_EPS = 1e-5f;

// ---- device scratch (no allocations allowed) ----
__device__ double g_mom[27];          // [0..5] = sum x_k ; [6..26] = upper-tri sum x_a*x_b
__device__ float  g_Wc[INF][OUTF];    // scale_j * W[j][k], stored [k][j]
__device__ float  g_c[OUTF];          // beta_j + scale_j*(b_j - mean_j)
__device__ unsigned int g_oddor;      // OR of odd 32-bit words of indices (0 => int64 layout)

// ---------------------------------------------------------------------------
// 0) per-launch scratch init (graph replays require re-zeroing every call)
// ---------------------------------------------------------------------------
__global__ void init_kernel() {
    int t = threadIdx.x;
    if (t < 27) g_mom[t] = 0.0;
    if (t == 31) g_oddor = 0u;
}

// ---------------------------------------------------------------------------
// 1) moments: S[6], M[21] over all points (48 MB streamed read)
// ---------------------------------------------------------------------------
__global__ void __launch_bounds__(256) moments_kernel(const float* __restrict__ x, int n) {
    float s[27];
    #pragma unroll
    for (int i = 0; i < 27; i++) s[i] = 0.f;

    int stride = gridDim.x * blockDim.x;
    for (int i = blockIdx.x * blockDim.x + threadIdx.x; i < n; i += stride) {
        const float2* p = (const float2*)(x + (size_t)i * INF);   // 8B aligned (24B stride)
        float2 a = p[0], b = p[1], c = p[2];
        float v[6] = {a.x, a.y, b.x, b.y, c.x, c.y};
        int t = 6;
        #pragma unroll
        for (int A = 0; A < 6; A++) {
            s[A] += v[A];
            #pragma unroll
            for (int B = A; B < 6; B++) s[t++] += v[A] * v[B];
        }
    }
    // warp reduce all 27
    #pragma unroll
    for (int i = 0; i < 27; i++) {
        #pragma unroll
        for (int off = 16; off > 0; off >>= 1)
            s[i] += __shfl_down_sync(0xffffffffu, s[i], off);
    }
    __shared__ float part[27][8];
    int lane = threadIdx.x & 31, warp = threadIdx.x >> 5;
    if (lane == 0) {
        #pragma unroll
        for (int i = 0; i < 27; i++) part[i][warp] = s[i];
    }
    __syncthreads();
    if (threadIdx.x < 27) {
        float tot = 0.f;
        int nw = blockDim.x >> 5;
        for (int w = 0; w < nw; w++) tot += part[threadIdx.x][w];
        atomicAdd(&g_mom[threadIdx.x], (double)tot);   // 27 * nblocks atomics, cheap
    }
}

// ---------------------------------------------------------------------------
// 1b) detect indices dtype: int64 pairs (values<512 => odd 32-bit words all 0)
//     vs int32 pairs (odd words are random y-indices). Scan first 2MB (safe in
//     both layouts: int32 layout has 2n words >= scan range).
// ---------------------------------------------------------------------------
__global__ void __launch_bounds__(256) detect_kernel(const unsigned int* __restrict__ w, int nwords) {
    unsigned int acc = 0;
    int stride = gridDim.x * blockDim.x;
    for (int i = blockIdx.x * blockDim.x + threadIdx.x; i * 2 + 1 < nwords; i += stride)
        acc |= w[i * 2 + 1];
    #pragma unroll
    for (int off = 16; off > 0; off >>= 1)
        acc |= __shfl_down_sync(0xffffffffu, acc, off);
    if ((threadIdx.x & 31) == 0 && acc) atomicOr(&g_oddor, acc);
}

// ---------------------------------------------------------------------------
// 2) finalize: fold BN into per-feature affine (1 block, 64 threads)
// ---------------------------------------------------------------------------
__global__ void finalize_kernel(const float* __restrict__ W, const float* __restrict__ b,
                                const float* __restrict__ gamma, const float* __restrict__ beta,
                                double inv_n) {
    int j = threadIdx.x;
    if (j >= OUTF) return;
    double S[6], M[21], w[6];
    for (int k = 0; k < 6; k++)  S[k] = g_mom[k];
    for (int t = 0; t < 21; t++) M[t] = g_mom[6 + t];
    for (int k = 0; k < 6; k++)  w[k] = (double)W[j * 6 + k];
    double bj = (double)b[j];

    double dot = 0.0;
    for (int k = 0; k < 6; k++) dot += w[k] * S[k];
    double q = 0.0; int t = 0;
    for (int A = 0; A < 6; A++)
        for (int B = A; B < 6; B++) {
            double term = w[A] * w[B] * M[t++];
            q += (A == B) ? term : 2.0 * term;
        }
    double mean = dot * inv_n + bj;
    double e2   = (q + 2.0 * bj * dot) * inv_n + bj * bj;
    double var  = e2 - mean * mean;
    double scale = (double)gamma[j] / sqrt(var + (double)BN_EPS);

    for (int k = 0; k < 6; k++) g_Wc[k][j] = (float)(scale * w[k]);
    g_c[j] = (float)((double)beta[j] + scale * (bj - mean));
}

// ---------------------------------------------------------------------------
// 3) fused linear+BN+relu + scatter-add (red.global.add.v4.f32, sm_90+)
// ---------------------------------------------------------------------------
__global__ void __launch_bounds__(256) scatter_kernel(const float* __restrict__ x,
                                                      const void* __restrict__ idx,
                                                      float* __restrict__ grid, int n) {
    __shared__ float sW[INF][OUTF];
    __shared__ float sc[OUTF];
    for (int t = threadIdx.x; t < INF * OUTF; t += blockDim.x)
        ((float*)sW)[t] = ((const float*)g_Wc)[t];
    if (threadIdx.x < OUTF) sc[threadIdx.x] = g_c[threadIdx.x];
    int is64 = (g_oddor == 0u);
    __syncthreads();

    int i = blockIdx.x * blockDim.x + threadIdx.x;
    if (i >= n) return;

    const float2* p = (const float2*)(x + (size_t)i * INF);
    float2 a = p[0], b2 = p[1], c2 = p[2];
    float v[6] = {a.x, a.y, b2.x, b2.y, c2.x, c2.y};

    int ix, iy;
    if (is64) {
        longlong2 id = ((const longlong2*)idx)[i];
        ix = (int)id.x; iy = (int)id.y;
    } else {
        int2 id = ((const int2*)idx)[i];
        ix = id.x; iy = id.y;
    }
    float* cell = grid + (size_t)((ix << 9) + iy) * OUTF;   // 16B-aligned per 4-group

    #pragma unroll
    for (int jg = 0; jg < OUTF / 4; jg++) {
        int j = jg * 4;
        float4 acc = *(const float4*)&sc[j];
        #pragma unroll
        for (int k = 0; k < 6; k++) {
            float4 w = *(const float4*)&sW[k][j];     // broadcast LDS.128, conflict-free
            acc.x = fmaf(v[k], w.x, acc.x);
            acc.y = fmaf(v[k], w.y, acc.y);
            acc.z = fmaf(v[k], w.z, acc.z);
            acc.w = fmaf(v[k], w.w, acc.w);
        }
        acc.x = fmaxf(acc.x, 0.f);
        acc.y = fmaxf(acc.y, 0.f);
        acc.z = fmaxf(acc.z, 0.f);
        acc.w = fmaxf(acc.w, 0.f);
        asm volatile("red.global.add.v4.f32 [%0], {%1, %2, %3, %4};"
                     :: "l"(cell + j), "f"(acc.x), "f"(acc.y), "f"(acc.z), "f"(acc.w)
                     : "memory");
    }
}

// ---------------------------------------------------------------------------
extern "C" void kernel_launch(void* const* d_in, const int* in_sizes, int n_in,
                              void* d_out, int out_size) {
    const float* x     = (const float*)d_in[0];
    const void*  idx   = d_in[1];                 // int64 or int32 pairs; detected on-device
    const float* W     = (const float*)d_in[2];
    const float* b     = (const float*)d_in[3];
    const float* gamma = (const float*)d_in[4];
    const float* beta  = (const float*)d_in[5];
    float* out = (float*)d_out;

    int n = in_sizes[0] / INF;                    // number of points

    init_kernel<<<1, 32>>>();
    moments_kernel<<<1184, 256>>>(x, n);

    // scan first min(2n, 2^19) 32-bit words (safe in the smaller int32 layout)
    int nwords = 2 * n; if (nwords > (1 << 19)) nwords = (1 << 19);
    detect_kernel<<<64, 256>>>((const unsigned int*)idx, nwords);

    finalize_kernel<<<1, 64>>>(W, b, gamma, beta, 1.0 / (double)n);

    cudaMemsetAsync(d_out, 0, (size_t)out_size * sizeof(float), 0);
    scatter_kernel<<<(n + 255) / 256, 256>>>(x, idx, out, n);
}